// round 16
// baseline (speedup 1.0000x reference)
#include <cuda_runtime.h>
#include <cuda_bf16.h>
#include <math.h>
#include <stdint.h>

// ---------------- problem constants ----------------
static constexpr int BB   = 4;
static constexpr int KK   = 256;
static constexpr int NS   = 1024;      // seeds
static constexpr int CF   = 256;       // seed feature channels
static constexpr int GPP  = 64;        // grid points per proposal
static constexpr int QQ   = KK * GPP;  // 16384 queries per batch
static constexpr int M1   = BB * QQ;   // 65536 rows for conv layers
static constexpr int CIN0 = CF + 3;    // 259 logical input channels
static constexpr int KPH0 = 288;       // padded logical K for layer0 (9 chunks of 32)
static constexpr int HH   = 128;
static constexpr int MFC  = BB * KK;   // 1024 rows for FC layers
static constexpr int IOUS = 18;
static constexpr int OUTC = 77;
static constexpr int KPP  = 20;        // padded pairs per SMEM row (16 used + 4 pad)

// ---------------- scratch (static device memory; no allocations) ----------------
__device__ float g_rel[M1 * 3];
__device__ float g_featT[BB * NS * CF];        // [b][n][c]
__device__ int   g_idx3[M1 * 3];
__device__ float g_w3[M1 * 3];
__device__ float g_Y1[(long long)M1 * HH];
__device__ float g_Y2[(long long)M1 * HH];
__device__ float g_F [MFC * HH];               // RAW maxpool output (pre-BN3)
__device__ float g_N1[MFC * HH];
__device__ float g_N2[MFC * HH];
__device__ float g_part[512 * 256];            // per-CTA partial BN stats
__device__ float g_scale[5 * 128];
__device__ float g_shift[5 * 128];
// pre-split packed-bf16 weights, layout [ch][n][kp16]; W0 permuted+padded
__device__ uint32_t g_W0H[9 * 128 * 16], g_W0L[9 * 128 * 16];
__device__ uint32_t g_W1H[4 * 128 * 16], g_W1L[4 * 128 * 16];
__device__ uint32_t g_W2H[4 * 128 * 16], g_W2L[4 * 128 * 16];

// ---------------- small helpers ----------------
// split two fp32 values into packed-bf16 (hi pair, lo pair); word = {k_even, k_odd}
__device__ __forceinline__ void split2_bf16(float v0, float v1, uint32_t& hi, uint32_t& lo) {
    __nv_bfloat16 h0 = __float2bfloat16_rn(v0);
    __nv_bfloat16 h1 = __float2bfloat16_rn(v1);
    float l0 = v0 - __bfloat162float(h0);
    float l1 = v1 - __bfloat162float(h1);
    __nv_bfloat162 hp = __halves2bfloat162(h0, h1);
    __nv_bfloat162 lp = __floats2bfloat162_rn(l0, l1);
    hi = *reinterpret_cast<uint32_t*>(&hp);
    lo = *reinterpret_cast<uint32_t*>(&lp);
}

__device__ __forceinline__ void mma_bf16(float& c0, float& c1, float& c2, float& c3,
                                         uint32_t a0, uint32_t a1, uint32_t a2, uint32_t a3,
                                         uint32_t b0, uint32_t b1) {
    asm volatile(
        "mma.sync.aligned.m16n8k16.row.col.f32.bf16.bf16.f32 "
        "{%0,%1,%2,%3}, {%4,%5,%6,%7}, {%8,%9}, {%0,%1,%2,%3};"
        : "+f"(c0), "+f"(c1), "+f"(c2), "+f"(c3)
        : "r"(a0), "r"(a1), "r"(a2), "r"(a3), "r"(b0), "r"(b1));
}

__device__ __forceinline__ void ldsm_x4(uint32_t& r0, uint32_t& r1, uint32_t& r2, uint32_t& r3,
                                        uint32_t addr) {
    asm volatile("ldmatrix.sync.aligned.m8n8.x4.shared.b16 {%0,%1,%2,%3}, [%4];"
                 : "=r"(r0), "=r"(r1), "=r"(r2), "=r"(r3) : "r"(addr));
}

__device__ __forceinline__ void cp_async16(uint32_t smem_addr, const void* gptr) {
    asm volatile("cp.async.cg.shared.global [%0], [%1], 16;"
                 :: "r"(smem_addr), "l"(gptr));
}
__device__ __forceinline__ void cp_async_commit() {
    asm volatile("cp.async.commit_group;");
}
__device__ __forceinline__ void cp_async_wait0() {
    asm volatile("cp.async.wait_group 0;");
}

// ---------------- merged weight prep: fp32 -> packed bf16 hi/lo, [ch][n][kp16] ----------------
__global__ void k_prepW(const float* __restrict__ W0,
                        const float* __restrict__ W1,
                        const float* __restrict__ W2) {
    int t = blockIdx.x * blockDim.x + threadIdx.x;
    if (t < 144 * 128) {
        int kp = t >> 7, n = t & 127;
        int k0 = 2 * kp, k1 = 2 * kp + 1;
        float v0 = 0.f, v1 = 0.f;
        if (k0 < CIN0) { int kl = (k0 < 256) ? k0 + 3 : k0 - 256; v0 = W0[n * CIN0 + kl]; }
        if (k1 < CIN0) { int kl = (k1 < 256) ? k1 + 3 : k1 - 256; v1 = W0[n * CIN0 + kl]; }
        uint32_t hi, lo;
        split2_bf16(v0, v1, hi, lo);
        int dst = (((kp >> 4) * 128) + n) * 16 + (kp & 15);
        g_W0H[dst] = hi; g_W0L[dst] = lo;
    } else {
        int u = t - 144 * 128;
        const float* W  = (u < 64 * 128) ? W1 : W2;
        uint32_t* WH    = (u < 64 * 128) ? g_W1H : g_W2H;
        uint32_t* WL    = (u < 64 * 128) ? g_W1L : g_W2L;
        if (u >= 64 * 128) u -= 64 * 128;
        int kp = u >> 7, n = u & 127;
        float v0 = W[n * 128 + 2 * kp];
        float v1 = W[n * 128 + 2 * kp + 1];
        uint32_t hi, lo;
        split2_bf16(v0, v1, hi, lo);
        int dst = (((kp >> 4) * 128) + n) * 16 + (kp & 15);
        WH[dst] = hi; WL[dst] = lo;
    }
}

// ---------------- stage-1 kernels ----------------

// seed_features [b][c][n] -> g_featT [b][n][c]
__global__ void k_transpose(const float* __restrict__ feat) {
    __shared__ float tile[32][33];
    int b  = blockIdx.z;
    int n0 = blockIdx.x * 32;
    int c0 = blockIdx.y * 32;
    const float* src = feat    + (long long)b * CF * NS;
    float*       dst = g_featT + (long long)b * NS * CF;
#pragma unroll
    for (int r = 0; r < 4; ++r) {
        int c = c0 + threadIdx.y + r * 8;
        tile[threadIdx.y + r * 8][threadIdx.x] = src[c * NS + n0 + threadIdx.x];
    }
    __syncthreads();
#pragma unroll
    for (int r = 0; r < 4; ++r) {
        int n = n0 + threadIdx.y + r * 8;
        dst[n * CF + c0 + threadIdx.x] = tile[threadIdx.x][threadIdx.y + r * 8];
    }
}

// fused grid-point + 3-NN, 4-way sliced: 4 threads per query, each scans 256 seeds
// (sp.w = -0.5*|p|^2; maximize t = q.p - 0.5|p|^2, equivalent to min |q-p|^2),
// then slice-ordered merge of 12 candidates (strict > keeps first-occurrence ties).
__global__ void k_threenn(const float* __restrict__ center,
                          const float* __restrict__ size_,
                          const float* __restrict__ heading,
                          const float* __restrict__ seed_xyz) {
    __shared__ float4 sp[NS];
    __shared__ float  candT[32][12];
    __shared__ int    candI[32][12];
    int b    = blockIdx.x >> 9;            // 512 blocks per batch (QQ/32)
    int qloc = (blockIdx.x & 511) * 32;
    int tid  = threadIdx.x;                // 128 threads
    for (int i = tid; i < NS; i += 128) {
        float x = seed_xyz[((long long)b * NS + i) * 3 + 0];
        float y = seed_xyz[((long long)b * NS + i) * 3 + 1];
        float z = seed_xyz[((long long)b * NS + i) * 3 + 2];
        sp[i] = make_float4(x, y, z, -0.5f * (x * x + y * y + z * z));
    }
    __syncthreads();

    int qi = tid >> 2;                     // 0..31 query within block
    int sl = tid & 3;                      // slice 0..3
    int q  = qloc + qi;
    int m  = b * QQ + q;
    int g  = m & 63;
    int bk = m >> 6;
    float sx = size_[bk * 3 + 0], sy = size_[bk * 3 + 1], sz = size_[bk * 3 + 2];
    float h  = heading[bk];
    float ch = cosf(h), sh = sinf(h);
    float gx = -1.f + (float)( g >> 4      ) * (2.f / 3.f);
    float gy = -1.f + (float)((g >> 2) & 3 ) * (2.f / 3.f);
    float gz = -1.f + (float)( g       & 3 ) * (2.f / 3.f);
    float ax = gx * sx, ay = gy * sy, az = gz * sz;
    float rx = ax * ch - ay * sh;
    float ry = ax * sh + ay * ch;
    float rz = az;
    float qx = rx + center[bk * 3 + 0];
    float qy = ry + center[bk * 3 + 1];
    float qz = rz + center[bk * 3 + 2];
    if (sl == 0) {
        g_rel[m * 3 + 0] = rx;
        g_rel[m * 3 + 1] = ry;
        g_rel[m * 3 + 2] = rz;
    }

    float t0 = -1e30f, t1 = -1e30f, t2 = -1e30f;
    int   i0 = 0, i1 = 0, i2 = 0;
    const int nb = sl * 256;
#pragma unroll 4
    for (int n = nb; n < nb + 256; ++n) {
        float4 p = sp[n];
        float t = fmaf(qx, p.x, fmaf(qy, p.y, fmaf(qz, p.z, p.w)));
        if (t > t2) {
            if (t > t1) {
                t2 = t1; i2 = i1;
                if (t > t0) { t1 = t0; i1 = i0; t0 = t; i0 = n; }
                else        { t1 = t;  i1 = n; }
            } else { t2 = t; i2 = n; }
        }
    }
    candT[qi][sl * 3 + 0] = t0; candI[qi][sl * 3 + 0] = i0;
    candT[qi][sl * 3 + 1] = t1; candI[qi][sl * 3 + 1] = i1;
    candT[qi][sl * 3 + 2] = t2; candI[qi][sl * 3 + 2] = i2;
    __syncthreads();

    if (sl == 0) {
        // merge 12 candidates in slice order (ascending index ranges; strict > ties)
        float m0 = -1e30f, m1 = -1e30f, m2 = -1e30f;
        int   j0 = 0, j1 = 0, j2 = 0;
#pragma unroll
        for (int c = 0; c < 12; ++c) {
            float t = candT[qi][c];
            int   i = candI[qi][c];
            if (t > m2) {
                if (t > m1) {
                    m2 = m1; j2 = j1;
                    if (t > m0) { m1 = m0; j1 = j0; m0 = t; j0 = i; }
                    else        { m1 = t;  j1 = i; }
                } else { m2 = t; j2 = i; }
            }
        }
        int ii[3] = {j0, j1, j2};
        float w[3];
#pragma unroll
        for (int j = 0; j < 3; ++j) {
            float4 p = sp[ii[j]];
            float dx = p.x - qx, dy = p.y - qy, dz = p.z - qz;
            float dist = sqrtf(dx * dx + dy * dy + dz * dz);
            w[j] = 1.f / (dist + 1e-8f);
        }
        float inv = 1.f / (w[0] + w[1] + w[2]);
#pragma unroll
        for (int j = 0; j < 3; ++j) {
            g_idx3[m * 3 + j] = ii[j];
            g_w3[m * 3 + j]   = w[j] * inv;
        }
    }
}

// ---- split-bf16 tensor-core GEMM, ldmatrix fragment loads, fused epilogue ----
// (structure identical to the measured 274.4us kernel; GATHER tail chunk runs
//  only its first k16 step — pairs 8..15 of chunk 8 are all-zero.)
template <bool BNA, bool GATHER, bool POOL, bool STOREC>
__global__ void __launch_bounds__(256, 2)
k_gemm_bf(const float* __restrict__ A, int lda,
          const uint32_t* __restrict__ WHg,
          const uint32_t* __restrict__ WLg,
          const float* __restrict__ bias,
          const float* __restrict__ scl,
          const float* __restrict__ shf,
          float* __restrict__ C,
          float* __restrict__ partOut,
          float* __restrict__ poolOut) {
    __shared__ uint32_t AsH[128][KPP];
    __shared__ uint32_t AsL[128][KPP];
    __shared__ uint32_t WsH[128][KPP];
    __shared__ uint32_t WsL[128][KPP];
    __shared__ float redS[2][128];
    __shared__ float redQ[2][128];
    __shared__ float redM[2][128];

    const int tid  = threadIdx.x;
    const int lane = tid & 31;
    const int warp = tid >> 5;
    const int g    = lane >> 2;        // 0..7
    const int q    = lane & 3;         // 0..3
    const int wm   = warp & 1;         // 2 warps over M
    const int wn   = warp >> 1;        // 4 warps over N
    const int bm   = blockIdx.x * 128;

    float acc[4][4][4];
#pragma unroll
    for (int i = 0; i < 4; ++i)
#pragma unroll
        for (int j = 0; j < 4; ++j)
#pragma unroll
            for (int r = 0; r < 4; ++r) acc[i][j][r] = 0.f;

    const int ldrow = tid >> 1;         // 0..127
    const int ldkv  = (tid & 1) * 16;   // 0 or 16
    const int kp0   = ldkv / 2;         // 0 or 8
    const int NCH   = GATHER ? (KPH0 / 32) : 4;

    // ldmatrix lane addresses
    const int arow = lane & 15;
    const int akp  = (lane >> 4) * 4;
    uint32_t aAdrH[4], aAdrL[4];
#pragma unroll
    for (int mt = 0; mt < 4; ++mt) {
        int r = wm * 64 + mt * 16 + arow;
        aAdrH[mt] = (uint32_t)__cvta_generic_to_shared(&AsH[r][akp]);
        aAdrL[mt] = (uint32_t)__cvta_generic_to_shared(&AsL[r][akp]);
    }
    const int bcol = wn * 32 + ((lane >> 4) * 8) + (lane & 7);
    const int bkp  = ((lane >> 3) & 1) * 4;
    uint32_t bAdrH[2], bAdrL[2];
#pragma unroll
    for (int t = 0; t < 2; ++t) {
        bAdrH[t] = (uint32_t)__cvta_generic_to_shared(&WsH[bcol + t * 16][bkp]);
        bAdrL[t] = (uint32_t)__cvta_generic_to_shared(&WsL[bcol + t * 16][bkp]);
    }

    // W cp.async mapping: n = tid>>1, kp half = tid&1 -> coalesced
    const int wcn = tid >> 1;
    const int wch = (tid & 1) * 8;
    const uint32_t dWH0 = (uint32_t)__cvta_generic_to_shared(&WsH[wcn][wch]);
    const uint32_t dWH1 = (uint32_t)__cvta_generic_to_shared(&WsH[wcn][wch + 4]);
    const uint32_t dWL0 = (uint32_t)__cvta_generic_to_shared(&WsL[wcn][wch]);
    const uint32_t dWL1 = (uint32_t)__cvta_generic_to_shared(&WsL[wcn][wch + 4]);

    // GATHER state (row fixed for the whole k-loop)
    const float *gf0 = nullptr, *gf1 = nullptr, *gf2 = nullptr;
    float gw0 = 0.f, gw1 = 0.f, gw2 = 0.f;
    float grel[3] = {0.f, 0.f, 0.f};
    if (GATHER) {
        const int m = bm + ldrow;
        const int b = m >> 14;
        int i0 = g_idx3[m * 3 + 0], i1 = g_idx3[m * 3 + 1], i2 = g_idx3[m * 3 + 2];
        gw0 = g_w3[m * 3 + 0]; gw1 = g_w3[m * 3 + 1]; gw2 = g_w3[m * 3 + 2];
        gf0 = g_featT + ((long long)b * NS + i0) * CF;
        gf1 = g_featT + ((long long)b * NS + i1) * CF;
        gf2 = g_featT + ((long long)b * NS + i2) * CF;
        grel[0] = g_rel[m * 3 + 0];
        grel[1] = g_rel[m * 3 + 1];
        grel[2] = g_rel[m * 3 + 2];
    }

    float vA[16];
    if (!GATHER) {
        const float* ap = A + (long long)(bm + ldrow) * lda + ldkv;
        float4 u0 = *(const float4*)(ap + 0);
        float4 u1 = *(const float4*)(ap + 4);
        float4 u2 = *(const float4*)(ap + 8);
        float4 u3 = *(const float4*)(ap + 12);
        vA[0]=u0.x; vA[1]=u0.y; vA[2]=u0.z; vA[3]=u0.w;
        vA[4]=u1.x; vA[5]=u1.y; vA[6]=u1.z; vA[7]=u1.w;
        vA[8]=u2.x; vA[9]=u2.y; vA[10]=u2.z; vA[11]=u2.w;
        vA[12]=u3.x; vA[13]=u3.y; vA[14]=u3.z; vA[15]=u3.w;
    }

    for (int ch = 0; ch < NCH; ++ch) {
        const int k0 = ch * 32;
        // ---- issue async W copy (overlaps the A build below) ----
        {
            const uint32_t* sH = WHg + ((ch * 128 + wcn) * 16) + wch;
            const uint32_t* sL = WLg + ((ch * 128 + wcn) * 16) + wch;
            cp_async16(dWH0, sH);
            cp_async16(dWH1, sH + 4);
            cp_async16(dWL0, sL);
            cp_async16(dWL1, sL + 4);
            cp_async_commit();
        }
        // ---- build + split A chunk -> SMEM ([m][kp], 2x STS.128 per plane) ----
        {
            float v[16];
            if (GATHER) {
                const int kbase = k0 + ldkv;
                if (kbase < 256) {
#pragma unroll
                    for (int r4 = 0; r4 < 4; ++r4) {
                        float4 a  = *(const float4*)(gf0 + kbase + r4 * 4);
                        float4 bq = *(const float4*)(gf1 + kbase + r4 * 4);
                        float4 cq = *(const float4*)(gf2 + kbase + r4 * 4);
                        v[r4 * 4 + 0] = gw0 * a.x + gw1 * bq.x + gw2 * cq.x;
                        v[r4 * 4 + 1] = gw0 * a.y + gw1 * bq.y + gw2 * cq.y;
                        v[r4 * 4 + 2] = gw0 * a.z + gw1 * bq.z + gw2 * cq.z;
                        v[r4 * 4 + 3] = gw0 * a.w + gw1 * bq.w + gw2 * cq.w;
                    }
                } else {
#pragma unroll
                    for (int i = 0; i < 16; ++i) v[i] = 0.f;
                    if (kbase == 256) { v[0] = grel[0]; v[1] = grel[1]; v[2] = grel[2]; }
                }
            } else {
#pragma unroll
                for (int i = 0; i < 16; ++i) v[i] = vA[i];
                if (BNA) {
#pragma unroll
                    for (int i = 0; i < 16; ++i) {
                        int k = k0 + ldkv + i;   // KDIM=128 in BNA mode: always valid
                        v[i] = fmaxf(v[i] * scl[k] + shf[k], 0.f);
                    }
                }
            }
            uint32_t hi[8], lo[8];
#pragma unroll
            for (int i = 0; i < 8; ++i)
                split2_bf16(v[2 * i], v[2 * i + 1], hi[i], lo[i]);
            *(uint4*)&AsH[ldrow][kp0]     = make_uint4(hi[0], hi[1], hi[2], hi[3]);
            *(uint4*)&AsH[ldrow][kp0 + 4] = make_uint4(hi[4], hi[5], hi[6], hi[7]);
            *(uint4*)&AsL[ldrow][kp0]     = make_uint4(lo[0], lo[1], lo[2], lo[3]);
            *(uint4*)&AsL[ldrow][kp0 + 4] = make_uint4(lo[4], lo[5], lo[6], lo[7]);
        }
        cp_async_wait0();
        __syncthreads();

        // ---- prefetch next A chunk (latency hidden behind MMAs; non-gather only) ----
        if (!GATHER && ch + 1 < NCH) {
            const float* ap = A + (long long)(bm + ldrow) * lda + (k0 + 32) + ldkv;
            float4 u0 = *(const float4*)(ap + 0);
            float4 u1 = *(const float4*)(ap + 4);
            float4 u2 = *(const float4*)(ap + 8);
            float4 u3 = *(const float4*)(ap + 12);
            vA[0]=u0.x; vA[1]=u0.y; vA[2]=u0.z; vA[3]=u0.w;
            vA[4]=u1.x; vA[5]=u1.y; vA[6]=u1.z; vA[7]=u1.w;
            vA[8]=u2.x; vA[9]=u2.y; vA[10]=u2.z; vA[11]=u2.w;
            vA[12]=u3.x; vA[13]=u3.y; vA[14]=u3.z; vA[15]=u3.w;
        }

        // ---- k16 steps; GATHER tail chunk (all-zero pairs 8..15) runs only kb=0 ----
        const int kbEnd = (GATHER && ch == NCH - 1) ? 8 : 16;
#pragma unroll
        for (int kb = 0; kb < 16; kb += 8) {
            if (kb >= kbEnd) break;
            const int kboff = kb * 4;   // bytes: 8 pairs * 4B
            uint32_t bH[4][2], bL[4][2];
#pragma unroll
            for (int t = 0; t < 2; ++t) {
                ldsm_x4(bH[2 * t][0], bH[2 * t][1], bH[2 * t + 1][0], bH[2 * t + 1][1],
                        bAdrH[t] + kboff);
                ldsm_x4(bL[2 * t][0], bL[2 * t][1], bL[2 * t + 1][0], bL[2 * t + 1][1],
                        bAdrL[t] + kboff);
            }
#pragma unroll
            for (int mt = 0; mt < 4; ++mt) {
                uint32_t aH0, aH1, aH2, aH3, aL0, aL1, aL2, aL3;
                ldsm_x4(aH0, aH1, aH2, aH3, aAdrH[mt] + kboff);
                ldsm_x4(aL0, aL1, aL2, aL3, aAdrL[mt] + kboff);
#pragma unroll
                for (int nt = 0; nt < 4; ++nt) {
                    mma_bf16(acc[mt][nt][0], acc[mt][nt][1], acc[mt][nt][2], acc[mt][nt][3],
                             aL0, aL1, aL2, aL3, bH[nt][0], bH[nt][1]);
                    mma_bf16(acc[mt][nt][0], acc[mt][nt][1], acc[mt][nt][2], acc[mt][nt][3],
                             aH0, aH1, aH2, aH3, bL[nt][0], bL[nt][1]);
                    mma_bf16(acc[mt][nt][0], acc[mt][nt][1], acc[mt][nt][2], acc[mt][nt][3],
                             aH0, aH1, aH2, aH3, bH[nt][0], bH[nt][1]);
                }
            }
        }
        __syncthreads();
    }

    // ---- fused epilogue: bias, optional store, BN stats partials, optional maxpool ----
    float bsv[4][2];
#pragma unroll
    for (int nt = 0; nt < 4; ++nt) {
        int col = wn * 32 + nt * 8 + q * 2;
        bsv[nt][0] = bias[col];
        bsv[nt][1] = bias[col + 1];
    }
    float s[4][2], s2[4][2], mx[4][2];
#pragma unroll
    for (int nt = 0; nt < 4; ++nt)
#pragma unroll
        for (int j = 0; j < 2; ++j) { s[nt][j] = 0.f; s2[nt][j] = 0.f; mx[nt][j] = -1e30f; }

#pragma unroll
    for (int mt = 0; mt < 4; ++mt) {
#pragma unroll
        for (int nt = 0; nt < 4; ++nt) {
            float v0 = acc[mt][nt][0] + bsv[nt][0];
            float v1 = acc[mt][nt][1] + bsv[nt][1];
            float v2 = acc[mt][nt][2] + bsv[nt][0];
            float v3 = acc[mt][nt][3] + bsv[nt][1];
            if (STOREC) {
                int col = wn * 32 + nt * 8 + q * 2;
                int r0  = bm + wm * 64 + mt * 16 + g;
                *(float2*)(C + (long long)r0 * 128 + col)       = make_float2(v0, v1);
                *(float2*)(C + (long long)(r0 + 8) * 128 + col) = make_float2(v2, v3);
            }
            s [nt][0] += v0 + v2;       s [nt][1] += v1 + v3;
            s2[nt][0] += v0 * v0 + v2 * v2;
            s2[nt][1] += v1 * v1 + v3 * v3;
            if (POOL) {
                mx[nt][0] = fmaxf(mx[nt][0], fmaxf(v0, v2));
                mx[nt][1] = fmaxf(mx[nt][1], fmaxf(v1, v3));
            }
        }
    }
#pragma unroll
    for (int nt = 0; nt < 4; ++nt)
#pragma unroll
        for (int j = 0; j < 2; ++j) {
#pragma unroll
            for (int mask = 4; mask <= 16; mask <<= 1) {
                s [nt][j] += __shfl_xor_sync(0xffffffff, s [nt][j], mask);
                s2[nt][j] += __shfl_xor_sync(0xffffffff, s2[nt][j], mask);
                if (POOL)
                    mx[nt][j] = fmaxf(mx[nt][j], __shfl_xor_sync(0xffffffff, mx[nt][j], mask));
            }
        }
    if (g == 0) {
#pragma unroll
        for (int nt = 0; nt < 4; ++nt)
#pragma unroll
            for (int j = 0; j < 2; ++j) {
                int col = wn * 32 + nt * 8 + q * 2 + j;
                redS[wm][col] = s[nt][j];
                redQ[wm][col] = s2[nt][j];
                if (POOL) redM[wm][col] = mx[nt][j];
            }
    }
    __syncthreads();
    if (tid < 128) {
        partOut[blockIdx.x * 256 + tid]       = redS[0][tid] + redS[1][tid];
        partOut[blockIdx.x * 256 + 128 + tid] = redQ[0][tid] + redQ[1][tid];
    }
    if (POOL) {
        poolOut[(blockIdx.x * 2 + (tid >> 7)) * 128 + (tid & 127)] = redM[tid >> 7][tid & 127];
    }
}

// reduce 512 per-CTA partials -> folded BN scale/shift (1 block, 512 threads)
__global__ void k_bnfin512(float Minv,
                           const float* __restrict__ gamma,
                           const float* __restrict__ beta,
                           int slot) {
    __shared__ float rs[4][128], rq[4][128];
    int c  = threadIdx.x & 127;
    int sl = threadIdx.x >> 7;
    float s = 0.f, q = 0.f;
    for (int b = sl * 128; b < sl * 128 + 128; ++b) {
        s += g_part[b * 256 + c];
        q += g_part[b * 256 + 128 + c];
    }
    rs[sl][c] = s; rq[sl][c] = q;
    __syncthreads();
    if (threadIdx.x < 128) {
        float S = rs[0][c] + rs[1][c] + rs[2][c] + rs[3][c];
        float Q = rq[0][c] + rq[1][c] + rq[2][c] + rq[3][c];
        float mean = S * Minv;
        float var  = Q * Minv - mean * mean;
        float rstd = rsqrtf(var + 1e-5f);
        float sc   = gamma[c] * rstd;
        g_scale[slot * 128 + c] = sc;
        g_shift[slot * 128 + c] = beta[c] - mean * sc;
    }
}

// -------- fp32 SIMT GEMM for FC layers: 64x128 tile, grid=16, fused BN-stats --------
template <int KDIM, bool BNA>
__global__ void __launch_bounds__(256)
k_gemm64(const float* __restrict__ A, int lda,
         const float* __restrict__ W,
         const float* __restrict__ bias,
         const float* __restrict__ scl,
         const float* __restrict__ shf,
         float* __restrict__ C,
         float* __restrict__ partOut) {
    __shared__ float As[16][64];
    __shared__ float Ws2[16][128];
    __shared__ float redS[16][128];
    __shared__ float redQ[16][128];
    int tid = threadIdx.x;
    int bm  = blockIdx.x * 64;
    int tx  = tid & 15, ty = tid >> 4;
    float acc[4][8];
#pragma unroll
    for (int i = 0; i < 4; ++i)
#pragma unroll
        for (int j = 0; j < 8; ++j) acc[i][j] = 0.f;

    const int KT = KDIM / 16;
    for (int kt = 0; kt < KT; ++kt) {
        int k0 = kt * 16;
        {
            int row = tid >> 2;
            int kv  = (tid & 3) * 4;
            int k   = k0 + kv;
            float4 v = *reinterpret_cast<const float4*>(A + (long long)(bm + row) * lda + k);
            if (BNA) {
                v.x = fmaxf(v.x * scl[k + 0] + shf[k + 0], 0.f);
                v.y = fmaxf(v.y * scl[k + 1] + shf[k + 1], 0.f);
                v.z = fmaxf(v.z * scl[k + 2] + shf[k + 2], 0.f);
                v.w = fmaxf(v.w * scl[k + 3] + shf[k + 3], 0.f);
            }
            As[kv + 0][row] = v.x;
            As[kv + 1][row] = v.y;
            As[kv + 2][row] = v.z;
            As[kv + 3][row] = v.w;
        }
        {
            int n  = tid >> 1;
            int kb = (tid & 1) * 8;
#pragma unroll
            for (int i = 0; i < 8; ++i)
                Ws2[kb + i][n] = W[n * KDIM + k0 + kb + i];
        }
        __syncthreads();
#pragma unroll
        for (int kk = 0; kk < 16; ++kk) {
            float a[4], w8[8];
            *reinterpret_cast<float4*>(&a[0])  = *reinterpret_cast<const float4*>(&As[kk][ty * 4]);
            *reinterpret_cast<float4*>(&w8[0]) = *reinterpret_cast<const float4*>(&Ws2[kk][tx * 8]);
            *reinterpret_cast<float4*>(&w8[4]) = *reinterpret_cast<const float4*>(&Ws2[kk][tx * 8 + 4]);
#pragma unroll
            for (int i = 0; i < 4; ++i)
#pragma unroll
                for (int j = 0; j < 8; ++j) acc[i][j] += a[i] * w8[j];
        }
        __syncthreads();
    }
    float bv[8];
#pragma unroll
    for (int j = 0; j < 8; ++j) bv[j] = bias[tx * 8 + j];
    float s[8], s2[8];
#pragma unroll
    for (int j = 0; j < 8; ++j) { s[j] = 0.f; s2[j] = 0.f; }
#pragma unroll
    for (int i = 0; i < 4; ++i) {
        long long off = (long long)(bm + ty * 4 + i) * 128 + tx * 8;
        float o[8];
#pragma unroll
        for (int j = 0; j < 8; ++j) {
            o[j] = acc[i][j] + bv[j];
            s[j] += o[j];
            s2[j] += o[j] * o[j];
        }
        *reinterpret_cast<float4*>(C + off)     = make_float4(o[0], o[1], o[2], o[3]);
        *reinterpret_cast<float4*>(C + off + 4) = make_float4(o[4], o[5], o[6], o[7]);
    }
#pragma unroll
    for (int j = 0; j < 8; ++j) {
        redS[ty][tx * 8 + j] = s[j];
        redQ[ty][tx * 8 + j] = s2[j];
    }
    __syncthreads();
    if (tid < 128) {
        float S = 0.f, Q = 0.f;
#pragma unroll
        for (int t = 0; t < 16; ++t) { S += redS[t][tid]; Q += redQ[t][tid]; }
        partOut[blockIdx.x * 256 + tid]       = S;
        partOut[blockIdx.x * 256 + 128 + tid] = Q;
    }
}

// reduce NB per-CTA partials -> folded BN scale/shift
__global__ void k_bnfin(int NB, float Minv,
                        const float* __restrict__ gamma,
                        const float* __restrict__ beta,
                        int slot) {
    int c = threadIdx.x;
    float s = 0.f, s2 = 0.f;
    for (int b = 0; b < NB; ++b) {
        s  += g_part[b * 256 + c];
        s2 += g_part[b * 256 + 128 + c];
    }
    float mean = s * Minv;
    float var  = s2 * Minv - mean * mean;
    float rstd = rsqrtf(var + 1e-5f);
    float sc   = gamma[c] * rstd;
    g_scale[slot * 128 + c] = sc;
    g_shift[slot * 128 + c] = beta[c] - mean * sc;
}

// BN5+ReLU on N2, project to the last 18 of 77 output channels
__global__ void k_final(const float* __restrict__ cw3,
                        const float* __restrict__ cb3,
                        float* __restrict__ out) {
    int t = blockIdx.x * blockDim.x + threadIdx.x;
    if (t >= MFC * IOUS) return;
    int j   = t % IOUS;
    int row = t / IOUS;
    int o   = (OUTC - IOUS) + j;
    const float* wrow = cw3 + o * 128;
    const float* x    = g_N2 + row * 128;
    float acc = cb3[o];
#pragma unroll 8
    for (int i = 0; i < 128; ++i) {
        float v = fmaxf(x[i] * g_scale[4 * 128 + i] + g_shift[4 * 128 + i], 0.f);
        acc += v * wrow[i];
    }
    out[t] = acc;
}

// ---------------- launcher ----------------
extern "C" void kernel_launch(void* const* d_in, const int* in_sizes, int n_in,
                              void* d_out, int out_size) {
    const float* center  = (const float*)d_in[0];
    const float* size_   = (const float*)d_in[1];
    const float* heading = (const float*)d_in[2];
    const float* sxyz    = (const float*)d_in[3];
    const float* sfeat   = (const float*)d_in[4];
    const float* w0  = (const float*)d_in[5];
    const float* b0  = (const float*)d_in[6];
    const float* g0  = (const float*)d_in[7];
    const float* be0 = (const float*)d_in[8];
    const float* w1  = (const float*)d_in[9];
    const float* b1  = (const float*)d_in[10];
    const float* g1  = (const float*)d_in[11];
    const float* be1 = (const float*)d_in[12];
    const float* w2  = (const float*)d_in[13];
    const float* b2  = (const float*)d_in[14];
    const float* g2  = (const float*)d_in[15];
    const float* be2 = (const float*)d_in[16];
    const float* cw1 = (const float*)d_in[17];
    const float* cb1 = (const float*)d_in[18];
    const float* g3  = (const float*)d_in[19];
    const float* be3 = (const float*)d_in[20];
    const float* cw2 = (const float*)d_in[21];
    const float* cb2 = (const float*)d_in[22];
    const float* g4  = (const float*)d_in[23];
    const float* be4 = (const float*)d_in[24];
    const float* cw3 = (const float*)d_in[25];
    const float* cb3 = (const float*)d_in[26];
    float* out = (float*)d_out;

    void *pY1, *pY2, *pF, *pN1, *pN2, *pSC, *pSH, *pPart;
    void *pW0H, *pW0L, *pW1H, *pW1L, *pW2H, *pW2L;
    cudaGetSymbolAddress(&pY1, g_Y1);
    cudaGetSymbolAddress(&pY2, g_Y2);
    cudaGetSymbolAddress(&pF,  g_F);
    cudaGetSymbolAddress(&pN1, g_N1);
    cudaGetSymbolAddress(&pN2, g_N2);
    cudaGetSymbolAddress(&pSC, g_scale);
    cudaGetSymbolAddress(&pSH, g_shift);
    cudaGetSymbolAddress(&pPart, g_part);
    cudaGetSymbolAddress(&pW0H, g_W0H);
    cudaGetSymbolAddress(&pW0L, g_W0L);
    cudaGetSymbolAddress(&pW1H, g_W1H);
    cudaGetSymbolAddress(&pW1L, g_W1L);
    cudaGetSymbolAddress(&pW2H, g_W2H);
    cudaGetSymbolAddress(&pW2L, g_W2L);
    float* Y1 = (float*)pY1;
    float* Y2 = (float*)pY2;
    float* F  = (float*)pF;
    float* N1 = (float*)pN1;
    float* N2 = (float*)pN2;
    float* SC = (float*)pSC;
    float* SH = (float*)pSH;
    float* PART = (float*)pPart;
    uint32_t* W0H = (uint32_t*)pW0H; uint32_t* W0L = (uint32_t*)pW0L;
    uint32_t* W1H = (uint32_t*)pW1H; uint32_t* W1L = (uint32_t*)pW1L;
    uint32_t* W2H = (uint32_t*)pW2H; uint32_t* W2L = (uint32_t*)pW2L;

    // stage 0: merged weight pre-split (one launch)
    k_prepW<<<(34816 + 255) / 256, 256>>>(w0, w1, w2);

    // stage 1: transpose + fused gridpoint/3-NN (4-way sliced scan)
    k_transpose<<<dim3(NS / 32, CF / 32, BB), dim3(32, 8)>>>(sfeat);
    k_threenn<<<M1 / 32, 128>>>(center, size_, heading, sxyz);

    // stage 2: SharedMLP on tensor cores; BN stats fused into each GEMM epilogue.
    k_gemm_bf<false, true, false, true><<<M1 / 128, 256>>>(
        nullptr, 0, W0H, W0L, b0, nullptr, nullptr, Y1, PART, nullptr);
    k_bnfin512<<<1, 512>>>(1.f / M1, g0, be0, 0);

    k_gemm_bf<true, false, false, true><<<M1 / 128, 256>>>(
        Y1, HH, W1H, W1L, b1, SC + 0 * 128, SH + 0 * 128, Y2, PART, nullptr);
    k_bnfin512<<<1, 512>>>(1.f / M1, g1, be1, 1);

    k_gemm_bf<true, false, true, false><<<M1 / 128, 256>>>(
        Y2, HH, W2H, W2L, b2, SC + 1 * 128, SH + 1 * 128, nullptr, PART, F);
    k_bnfin512<<<1, 512>>>(1.f / M1, g2, be2, 2);

    // stage 3: FC head (fp32 SIMT, 64-row tiles, fused BN stats). FC1 applies BN3+ReLU.
    k_gemm64<HH, true><<<MFC / 64, 256>>>(F, HH, cw1, cb1, SC + 2 * 128, SH + 2 * 128, N1, PART);
    k_bnfin<<<1, 128>>>(16, 1.f / MFC, g3, be3, 3);

    k_gemm64<HH, true><<<MFC / 64, 256>>>(N1, HH, cw2, cb2, SC + 3 * 128, SH + 3 * 128, N2, PART);
    k_bnfin<<<1, 128>>>(16, 1.f / MFC, g4, be4, 4);

    k_final<<<(MFC * IOUS + 255) / 256, 256>>>(cw3, cb3, out);
}